// round 1
// baseline (speedup 1.0000x reference)
#include <cuda_runtime.h>
#include <cuda_bf16.h>

#define Bq 32
#define Nq 325
#define Kq 20
#define S_IN 12
#define S_OUTq 12
#define Cq 10
#define Hq 48            // 4*S_OUT
#define BNq (Bq*Nq)      // 10400

__device__ float g_wh[BNq*S_OUTq];
__device__ float g_hx[BNq*Hq];
__device__ float g_hy[BNq*Hq];
__device__ double g_acc[3];   // [0]=wh_sum, [1]=dist_sum, [2]=cl_sum

__device__ __forceinline__ float leaky(float x){ return x >= 0.f ? x : 0.5f*x; }

__global__ void k_init(){
    if (threadIdx.x < 3) g_acc[threadIdx.x] = 0.0;
}

// one block per (b,n) row: wh (12), hx (48), hy (48)
__global__ void k1(const float* __restrict__ inp, const float* __restrict__ wW,
                   const float* __restrict__ wb,  const float* __restrict__ a1W){
    int bn = blockIdx.x;
    int t  = threadIdx.x;               // 48 threads
    __shared__ float s_in[S_IN];
    __shared__ float s_wh[S_OUTq];
    if (t < S_IN) s_in[t] = inp[bn*S_IN + t];
    __syncthreads();
    if (t < S_OUTq) {
        float acc = wb[t];
        #pragma unroll
        for (int i = 0; i < S_IN; i++) acc += s_in[i] * wW[i*S_OUTq + t];
        float v = leaky(acc);
        s_wh[t] = v;
        g_wh[bn*S_OUTq + t] = v;
    }
    __syncthreads();
    {   // hx[d], hy[d]   d = t in [0,48)
        float ax = 0.f, ay = 0.f;
        #pragma unroll
        for (int s = 0; s < S_OUTq; s++) {
            float w = s_wh[s];
            ax += w * a1W[s*Hq + t];
            ay += w * a1W[(S_OUTq + s)*Hq + t];
        }
        g_hx[bn*Hq + t] = ax;
        g_hy[bn*Hq + t] = ay;
    }
    if (t == 0) {
        float ssum = 0.f;
        #pragma unroll
        for (int s = 0; s < S_OUTq; s++) ssum += s_wh[s];
        atomicAdd(&g_acc[0], (double)ssum);
    }
}

// one block (128 thr) per (b,n): gather K neighbors, attention, softmax,
// output einsum, dist/cluster-loss.
__global__ __launch_bounds__(128) void k2(
        const float* __restrict__ a1b, const float* __restrict__ a2W,
        const float* __restrict__ a2b, const int* __restrict__ idx,
        float* __restrict__ out){
    int bn = blockIdx.x;
    int b  = bn / Nq;
    int t  = threadIdx.x;

    __shared__ __align__(16) float s_hx[Hq];
    __shared__ __align__(16) float s_a1b[Hq];
    __shared__ int   s_j[Kq];
    __shared__ __align__(16) float s_hid[Kq][Hq];
    __shared__ __align__(16) float s_att[Kq][12];   // 10 used, padded to 12 (zeros)
    __shared__ __align__(16) float s_wht[Kq][12];
    __shared__ __align__(16) float s_wtn[Kq][12];
    __shared__ __align__(16) float s_wT[Cq][Hq];    // a2_W transposed
    __shared__ float s_rd[4], s_rc[4];

    if (t < Kq) s_j[t] = idx[bn*Kq + t];
    if (t < Hq) { s_hx[t] = g_hx[bn*Hq + t]; s_a1b[t] = a1b[t]; }
    for (int i = t; i < Cq*Hq; i += 128) {
        int d = i % Hq, c = i / Hq;
        s_wT[c][d] = a2W[d*Cq + c];
    }
    __syncthreads();

    // hidden[k][d] = leaky(hx[d] + hy[j_k][d] + a1b[d])
    for (int i = t; i < Kq*Hq; i += 128) {
        int k = i / Hq, d = i % Hq;
        s_hid[k][d] = leaky(s_hx[d] + g_hy[(b*Nq + s_j[k])*Hq + d] + s_a1b[d]);
    }
    // wh_topk[k][s]
    for (int i = t; i < Kq*S_OUTq; i += 128) {
        int k = i / S_OUTq, s = i % S_OUTq;
        s_wht[k][s] = g_wh[(b*Nq + s_j[k])*S_OUTq + s];
    }
    __syncthreads();

    // attention[k][c] = leaky(hidden[k] . a2W[:,c] + a2b[c])  (200 vals)
    for (int i = t; i < Kq*Cq; i += 128) {
        int k = i / Cq, c = i % Cq;
        float acc = a2b[c];
        const float4* hv = (const float4*)s_hid[k];
        const float4* wv = (const float4*)s_wT[c];
        #pragma unroll
        for (int q = 0; q < Hq/4; q++) {
            float4 h = hv[q], w = wv[q];
            acc += h.x*w.x + h.y*w.y + h.z*w.z + h.w*w.w;
        }
        s_att[k][c] = leaky(acc);
    }
    __syncthreads();

    // softmax over c (threads 0..19) ; wtn (threads 64..83)
    if (t < Kq) {
        float m = -1e30f;
        #pragma unroll
        for (int c = 0; c < Cq; c++) m = fmaxf(m, s_att[t][c]);
        float e[Cq]; float sum = 0.f;
        #pragma unroll
        for (int c = 0; c < Cq; c++) { e[c] = expf(s_att[t][c] - m); sum += e[c]; }
        float inv = 1.f / sum;
        #pragma unroll
        for (int c = 0; c < Cq; c++) s_att[t][c] = e[c] * inv;
        s_att[t][10] = 0.f; s_att[t][11] = 0.f;
    } else if (t >= 64 && t < 64 + Kq) {
        int k = t - 64;
        float ss = 0.f;
        #pragma unroll
        for (int s = 0; s < S_OUTq; s++) ss += s_wht[k][s] * s_wht[k][s];
        float inv = 1.f / (sqrtf(ss) + 1e-8f);
        #pragma unroll
        for (int s = 0; s < S_OUTq; s++) s_wtn[k][s] = s_wht[k][s] * inv;
    }
    __syncthreads();

    // output[b,n,c,s] = sum_k am[k][c] * wht[k][s]   (120 vals, coalesced)
    for (int i = t; i < Cq*S_OUTq; i += 128) {
        int c = i / S_OUTq, s = i % S_OUTq;
        float acc = 0.f;
        #pragma unroll
        for (int k = 0; k < Kq; k++) acc += s_att[k][c] * s_wht[k][s];
        out[bn*Cq*S_OUTq + i] = acc;
    }

    // dist (all pairs) + cluster loss (off-diagonal)
    float dsum = 0.f, csum = 0.f;
    for (int i = t; i < Kq*Kq; i += 128) {
        int k = i / Kq, l = i % Kq;
        const float4* ak = (const float4*)s_wtn[k];
        const float4* al = (const float4*)s_wtn[l];
        float dist = 0.f;
        #pragma unroll
        for (int q = 0; q < 3; q++) {
            float4 x = ak[q], y = al[q];
            dist += x.x*y.x + x.y*y.y + x.z*y.z + x.w*y.w;
        }
        dsum += dist;
        if (k != l) {
            const float4* pk = (const float4*)s_att[k];
            const float4* pl = (const float4*)s_att[l];
            float p = 0.f;
            #pragma unroll
            for (int q = 0; q < 3; q++) {
                float4 x = pk[q], y = pl[q];
                p += x.x*y.x + x.y*y.y + x.z*y.z + x.w*y.w;
            }
            p = fminf(fmaxf(p, 1e-4f), 1.f - 1e-4f);
            float lp = logf(p);
            csum += (dist >= 0.5f) ? -lp : lp;   // cl = (1-2*same)*logp
        }
    }
    // block reduce
    #pragma unroll
    for (int o = 16; o; o >>= 1) {
        dsum += __shfl_down_sync(0xffffffffu, dsum, o);
        csum += __shfl_down_sync(0xffffffffu, csum, o);
    }
    if ((t & 31) == 0) { s_rd[t >> 5] = dsum; s_rc[t >> 5] = csum; }
    __syncthreads();
    if (t == 0) {
        float D  = s_rd[0] + s_rd[1] + s_rd[2] + s_rd[3];
        float CL = s_rc[0] + s_rc[1] + s_rc[2] + s_rc[3];
        atomicAdd(&g_acc[1], (double)D);
        atomicAdd(&g_acc[2], (double)CL);
    }
}

__global__ void k_fin(float* __restrict__ out, int out_size){
    if (threadIdx.x == 0) {
        out[out_size - 3] = (float)(g_acc[2] / (double)BNq);                 // cluster_loss
        out[out_size - 2] = (float)(g_acc[1] / (double)((long long)BNq*Kq*Kq)); // dist_mat.mean
        out[out_size - 1] = (float)(g_acc[0] / (double)((long long)BNq*S_OUTq)); // wh.mean
    }
}

extern "C" void kernel_launch(void* const* d_in, const int* in_sizes, int n_in,
                              void* d_out, int out_size) {
    // d_in order per metadata: 0 fushed_features (unused), 1 input_data, 2 w_W,
    // 3 w_b, 4 a1_W, 5 a1_b, 6 a2_W, 7 a2_b, 8 adj_mx_topk_index (int32)
    const float* input_data = (const float*)d_in[1];
    const float* wW  = (const float*)d_in[2];
    const float* wb  = (const float*)d_in[3];
    const float* a1W = (const float*)d_in[4];
    const float* a1b = (const float*)d_in[5];
    const float* a2W = (const float*)d_in[6];
    const float* a2b = (const float*)d_in[7];
    const int*   idx = (const int*)d_in[8];
    float* out = (float*)d_out;

    k_init<<<1, 32>>>();
    k1<<<BNq, 48>>>(input_data, wW, wb, a1W);
    k2<<<BNq, 128>>>(a1b, a2W, a2b, idx, out);
    k_fin<<<1, 32>>>(out, out_size);
}

// round 3
// speedup vs baseline: 1.9466x; 1.9466x over previous
#include <cuda_runtime.h>
#include <cuda_bf16.h>

#define Bq 32
#define Nq 325
#define Kq 20
#define S_IN 12
#define S_OUTq 12
#define Cq 10
#define Hq 48            // 4*S_OUT
#define BNq (Bq*Nq)      // 10400
#define PADH 52          // padded row stride (odd float4 count -> no bank conflicts)

__device__ float g_wh[BNq*S_OUTq];
__device__ float g_hx[BNq*Hq];
__device__ float g_hy[BNq*Hq];
__device__ float g_wT[Cq*PADH];          // a2_W transposed, padded
__device__ double g_acc[3] = {0.0, 0.0, 0.0};   // wh_sum, dist_sum, cl_sum
__device__ int g_counter = 0;

__device__ __forceinline__ float leaky(float x){ return x >= 0.f ? x : 0.5f*x; }

// ---------------- k1: warp per (b,n) row. 256 thr, 1300 blocks ----------------
__global__ __launch_bounds__(256) void k1(
        const float* __restrict__ inp, const float* __restrict__ wW,
        const float* __restrict__ wb,  const float* __restrict__ a1W,
        const float* __restrict__ a2W){
    int t = threadIdx.x;
    int warp = t >> 5, lane = t & 31;
    int bn = blockIdx.x * 8 + warp;

    if (blockIdx.x == 0) {   // transpose a2_W for k2 (coalesced f4 reads later)
        for (int i = t; i < Cq*Hq; i += 256) {
            int c = i / Hq, d = i % Hq;
            g_wT[c*PADH + d] = a2W[d*Cq + c];
        }
    }

    float whsum = 0.f;
    if (bn < BNq) {
        float xin = (lane < S_IN) ? inp[bn*S_IN + lane] : 0.f;
        float wh = (lane < S_OUTq) ? wb[lane] : 0.f;
        #pragma unroll
        for (int i = 0; i < S_IN; i++) {
            float xi = __shfl_sync(0xffffffffu, xin, i);
            if (lane < S_OUTq) wh += xi * wW[i*S_OUTq + lane];
        }
        wh = leaky(wh);
        if (lane < S_OUTq) { g_wh[bn*S_OUTq + lane] = wh; whsum = wh; }

        int d2 = 32 + (lane & 15);
        float ax = 0.f, ay = 0.f, ax2 = 0.f, ay2 = 0.f;
        #pragma unroll
        for (int s = 0; s < S_OUTq; s++) {
            float w = __shfl_sync(0xffffffffu, wh, s);
            ax  += w * a1W[s*Hq + lane];
            ay  += w * a1W[(S_OUTq+s)*Hq + lane];
            ax2 += w * a1W[s*Hq + d2];
            ay2 += w * a1W[(S_OUTq+s)*Hq + d2];
        }
        g_hx[bn*Hq + lane] = ax;
        g_hy[bn*Hq + lane] = ay;
        if (lane < 16) { g_hx[bn*Hq + d2] = ax2; g_hy[bn*Hq + d2] = ay2; }
    }
    // block-reduce wh sum, one atomic per block
    #pragma unroll
    for (int o = 16; o; o >>= 1) whsum += __shfl_down_sync(0xffffffffu, whsum, o);
    __shared__ float sred[8];
    if (lane == 0) sred[warp] = whsum;
    __syncthreads();
    if (t == 0) {
        float s = 0.f;
        #pragma unroll
        for (int w = 0; w < 8; w++) s += sred[w];
        atomicAdd(&g_acc[0], (double)s);
    }
}

// ---------------- k2: block per (b,n), 128 thr ----------------
__global__ __launch_bounds__(128) void k2(
        const float* __restrict__ a1b, const float* __restrict__ a2b,
        const int* __restrict__ idx, float* __restrict__ out, int out_size){
    int bn = blockIdx.x;
    int b  = bn / Nq;
    int t  = threadIdx.x;

    __shared__ int s_j[Kq];
    __shared__ __align__(16) float s_hxb[Hq];          // hx + a1_b pre-added
    __shared__ __align__(16) float s_hid[Kq][PADH];
    __shared__ __align__(16) float s_att[Kq][12];      // 10 used + zero pad
    __shared__ __align__(16) float s_wht[Kq][12];
    __shared__ __align__(16) float s_wT[Cq][PADH];
    __shared__ float s_inv[Kq], s_diag[Kq];
    __shared__ float s_rd[4], s_rc[4];

    // phase A: indices, hx+bias, weights
    if (t < Kq) s_j[t] = idx[bn*Kq + t];
    if (t < Hq/4) {
        float4 hx = ((const float4*)(g_hx + bn*Hq))[t];
        float4 bb = ((const float4*)a1b)[t];
        ((float4*)s_hxb)[t] = make_float4(hx.x+bb.x, hx.y+bb.y, hx.z+bb.z, hx.w+bb.w);
    }
    for (int i = t; i < Cq*12; i += 128) {     // 120 float4 items
        int c = i / 12, q = i % 12;
        ((float4*)s_wT[c])[q] = ((const float4*)(g_wT + c*PADH))[q];
    }
    __syncthreads();

    // phase B: hidden gather (240 f4), wh_topk gather (60 f4)
    for (int i = t; i < Kq*12; i += 128) {
        int k = i / 12, q = i % 12;
        float4 hy = ((const float4*)(g_hy + (b*Nq + s_j[k])*Hq))[q];
        float4 hb = ((const float4*)s_hxb)[q];
        float4 v = make_float4(leaky(hb.x+hy.x), leaky(hb.y+hy.y),
                               leaky(hb.z+hy.z), leaky(hb.w+hy.w));
        ((float4*)s_hid[k])[q] = v;
    }
    if (t < Kq*3) {
        int k = t / 3, q = t % 3;
        ((float4*)s_wht[k])[q] = ((const float4*)(g_wh + (b*Nq + s_j[k])*S_OUTq))[q];
    }
    __syncthreads();

    // phase C: attention[k][c], thread handles (k, c) and (k+10, c), shares wT[c]
    if (t < 100) {
        int c = t % Cq, k0 = t / Cq;
        float bias = a2b[c];
        float acc0 = bias, acc1 = bias;
        const float4* wv = (const float4*)s_wT[c];
        const float4* h0 = (const float4*)s_hid[k0];
        const float4* h1 = (const float4*)s_hid[k0+10];
        #pragma unroll
        for (int q = 0; q < 12; q++) {
            float4 w = wv[q], a = h0[q], e = h1[q];
            acc0 += a.x*w.x + a.y*w.y + a.z*w.z + a.w*w.w;
            acc1 += e.x*w.x + e.y*w.y + e.z*w.z + e.w*w.w;
        }
        s_att[k0][c]    = leaky(acc0);
        s_att[k0+10][c] = leaky(acc1);
    }
    __syncthreads();

    // phase D: softmax rows (threads 0..19); norms (threads 64..83)
    if (t < Kq) {
        float m = -1e30f;
        #pragma unroll
        for (int c = 0; c < Cq; c++) m = fmaxf(m, s_att[t][c]);
        float e[Cq]; float sum = 0.f;
        #pragma unroll
        for (int c = 0; c < Cq; c++) { e[c] = __expf(s_att[t][c] - m); sum += e[c]; }
        float inv = __fdividef(1.f, sum);
        #pragma unroll
        for (int c = 0; c < Cq; c++) s_att[t][c] = e[c] * inv;
        s_att[t][10] = 0.f; s_att[t][11] = 0.f;
    } else if (t >= 64 && t < 64 + Kq) {
        int k = t - 64;
        float ss = 0.f;
        const float4* w = (const float4*)s_wht[k];
        #pragma unroll
        for (int q = 0; q < 3; q++) {
            float4 x = w[q];
            ss += x.x*x.x + x.y*x.y + x.z*x.z + x.w*x.w;
        }
        float inv = __fdividef(1.f, sqrtf(ss) + 1e-8f);
        s_inv[k]  = inv;
        s_diag[k] = ss * inv * inv;
    }
    __syncthreads();

    // phase E: fused output einsum (30 f4 items) + upper-triangle dist/loss (210 items)
    float dsum = 0.f, csum = 0.f;
    for (int i = t; i < 240; i += 128) {
        if (i < 30) {
            int c = i / 3, q = i % 3;
            float4 acc = make_float4(0.f, 0.f, 0.f, 0.f);
            #pragma unroll
            for (int k = 0; k < Kq; k++) {
                float a = s_att[k][c];
                float4 w = ((const float4*)s_wht[k])[q];
                acc.x += a*w.x; acc.y += a*w.y; acc.z += a*w.z; acc.w += a*w.w;
            }
            ((float4*)(out + bn*Cq*S_OUTq))[i] = acc;
        } else {
            int p = i - 30;   // triangle index incl. diagonal, 210 items
            int k = (int)floorf((41.0f - sqrtf(1681.0f - 8.0f*(float)p)) * 0.5f);
            int offk = (41*k - k*k) >> 1;
            if (p < offk) { k--; offk = (41*k - k*k) >> 1; }
            else { int offn = (41*(k+1) - (k+1)*(k+1)) >> 1; if (p >= offn) { k++; offk = offn; } }
            int l = k + (p - offk);
            if (k == l) {
                dsum += s_diag[k];
            } else {
                const float4* ak = (const float4*)s_wht[k];
                const float4* al = (const float4*)s_wht[l];
                float d = 0.f;
                #pragma unroll
                for (int q = 0; q < 3; q++) {
                    float4 x = ak[q], y = al[q];
                    d += x.x*y.x + x.y*y.y + x.z*y.z + x.w*y.w;
                }
                d *= s_inv[k] * s_inv[l];
                dsum += 2.f * d;
                const float4* pk = (const float4*)s_att[k];
                const float4* pl = (const float4*)s_att[l];
                float pr = 0.f;
                #pragma unroll
                for (int q = 0; q < 3; q++) {
                    float4 x = pk[q], y = pl[q];
                    pr += x.x*y.x + x.y*y.y + x.z*y.z + x.w*y.w;
                }
                pr = fminf(fmaxf(pr, 1e-4f), 1.f - 1e-4f);
                float lp = __logf(pr);
                csum += (d >= 0.5f) ? -2.f*lp : 2.f*lp;
            }
        }
    }
    #pragma unroll
    for (int o = 16; o; o >>= 1) {
        dsum += __shfl_down_sync(0xffffffffu, dsum, o);
        csum += __shfl_down_sync(0xffffffffu, csum, o);
    }
    if ((t & 31) == 0) { s_rd[t >> 5] = dsum; s_rc[t >> 5] = csum; }
    __syncthreads();
    if (t == 0) {
        atomicAdd(&g_acc[1], (double)(s_rd[0] + s_rd[1] + s_rd[2] + s_rd[3]));
        atomicAdd(&g_acc[2], (double)(s_rc[0] + s_rc[1] + s_rc[2] + s_rc[3]));
        __threadfence();
        int done = atomicAdd(&g_counter, 1);
        if (done == BNq - 1) {   // last block finalizes + resets for next replay
            out[out_size - 3] = (float)(g_acc[2] / (double)BNq);
            out[out_size - 2] = (float)(g_acc[1] / (double)((long long)BNq*Kq*Kq));
            out[out_size - 1] = (float)(g_acc[0] / (double)((long long)BNq*S_OUTq));
            g_acc[0] = 0.0; g_acc[1] = 0.0; g_acc[2] = 0.0;
            g_counter = 0;
        }
    }
}

extern "C" void kernel_launch(void* const* d_in, const int* in_sizes, int n_in,
                              void* d_out, int out_size) {
    const float* input_data = (const float*)d_in[1];
    const float* wW  = (const float*)d_in[2];
    const float* wb  = (const float*)d_in[3];
    const float* a1W = (const float*)d_in[4];
    const float* a1b = (const float*)d_in[5];
    const float* a2W = (const float*)d_in[6];
    const float* a2b = (const float*)d_in[7];
    const int*   idx = (const int*)d_in[8];
    float* out = (float*)d_out;

    k1<<<(BNq + 7) / 8, 256>>>(input_data, wW, wb, a1W, a2W);
    k2<<<BNq, 128>>>(a1b, a2b, idx, out, out_size);
}